// round 14
// baseline (speedup 1.0000x reference)
#include <cuda_runtime.h>
#include <cuda_fp16.h>
#include <cstdint>
#include <math.h>

// Problem dims (fixed by the reference)
constexpr int B_  = 8;
constexpr int T_  = 200;
constexpr int U_  = 50;
constexpr int D_  = 512;
constexpr int J_  = 512;
constexpr int V_  = 1024;

constexpr int ME = B_ * T_;        // 1600
constexpr int MD = B_ * U_;        // 400
constexpr int MZ = B_ * T_ * U_;   // 80000

// Scratch (device globals: allocation-free per harness rules)
__device__ float  g_E[(size_t)ME * J_];
__device__ float  g_D[(size_t)MD * J_];
__device__ __half g_Zh[(size_t)MZ * J_];
__device__ __half g_Wh[(size_t)V_ * J_];
__device__ __half g_Eh[(size_t)ME * D_];     // h_enc fp16
__device__ __half g_Dh[(size_t)MD * D_];     // h_dec fp16
__device__ __half g_Weh[(size_t)J_ * D_];    // W_enc fp16
__device__ __half g_Wdh[(size_t)J_ * D_];    // W_dec fp16

// ---------------------------------------------------------------------------
__device__ __forceinline__ uint32_t smem_to_u32(const void* p) {
    uint32_t a;
    asm("{ .reg .u64 t; cvta.to.shared.u64 t, %1; cvt.u32.u64 %0, t; }"
        : "=r"(a) : "l"(p));
    return a;
}

#define CP_ASYNC16(saddr, gaddr) \
    asm volatile("cp.async.cg.shared.global [%0], [%1], 16;" :: "r"(saddr), "l"(gaddr) : "memory")
#define CP_ASYNC_COMMIT() asm volatile("cp.async.commit_group;" ::: "memory")

#define LDSM_X4(r0, r1, r2, r3, addr) \
    asm volatile("ldmatrix.sync.aligned.m8n8.x4.shared.b16 {%0,%1,%2,%3}, [%4];" \
        : "=r"(r0), "=r"(r1), "=r"(r2), "=r"(r3) : "r"(addr))

__device__ __forceinline__ float tanh_fast(float x) {
    float y;
    asm("tanh.approx.f32 %0, %1;" : "=f"(y) : "f"(x));
    return y;
}

__device__ __forceinline__ void mma_f16(float* d,
                                        uint32_t a0, uint32_t a1, uint32_t a2, uint32_t a3,
                                        uint32_t b0, uint32_t b1) {
    asm volatile(
        "mma.sync.aligned.m16n8k16.row.col.f32.f16.f16.f32 "
        "{%0,%1,%2,%3}, {%4,%5,%6,%7}, {%8,%9}, {%0,%1,%2,%3};"
        : "+f"(d[0]), "+f"(d[1]), "+f"(d[2]), "+f"(d[3])
        : "r"(a0), "r"(a1), "r"(a2), "r"(a3), "r"(b0), "r"(b1));
}

__device__ __forceinline__ uint32_t pack_h2(float x, float y) {
    __half2 h = __floats2half2_rn(x, y);
    return *reinterpret_cast<uint32_t*>(&h);
}

// Shared smem-row geometry for all mma kernels
constexpr int ROWH = 72;                         // 64 + 8 pad halves
constexpr int ROWB = ROWH * 2;                   // 144 B (16B-aligned, LDSM-safe)

// ---------------------------------------------------------------------------
// Convert kernel: plain fp32 -> fp16 for the 5 input tensors.
// ---------------------------------------------------------------------------
__global__ __launch_bounds__(256)
void convert_kernel(const float* __restrict__ h_enc,
                    const float* __restrict__ h_dec,
                    const float* __restrict__ W_enc,
                    const float* __restrict__ W_dec,
                    const float* __restrict__ W_out)
{
    const int z    = blockIdx.z;
    const int nthr = gridDim.x * 256;
    const int t0   = blockIdx.x * 256 + threadIdx.x;

    const float* src; __half* dst; int n;
    if      (z == 0) { src = h_enc; dst = g_Eh;  n = ME * D_; }
    else if (z == 1) { src = h_dec; dst = g_Dh;  n = MD * D_; }
    else if (z == 2) { src = W_enc; dst = g_Weh; n = J_ * D_; }
    else if (z == 3) { src = W_dec; dst = g_Wdh; n = J_ * D_; }
    else             { src = W_out; dst = g_Wh;  n = V_ * J_; }

    const int total8 = n / 8;
    for (int i = t0; i < total8; i += nthr) {
        float4 v0 = *reinterpret_cast<const float4*>(src + (size_t)i * 8);
        float4 v1 = *reinterpret_cast<const float4*>(src + (size_t)i * 8 + 4);
        uint4 st;
        st.x = pack_h2(v0.x, v0.y);
        st.y = pack_h2(v0.z, v0.w);
        st.z = pack_h2(v1.x, v1.y);
        st.w = pack_h2(v1.z, v1.w);
        *reinterpret_cast<uint4*>(dst + (size_t)i * 8) = st;
    }
}

// ---------------------------------------------------------------------------
// Layer-1 fp16 GEMM (K=512), fine tiles:
// BM=64, BN=64, BK=64, 128 threads (4 warps 2x2, warp tile 32x32).
// grid (8, 25, 2): z=0 -> E (bias b_enc), z=1 -> D (no bias, y<7).
// ---------------------------------------------------------------------------
constexpr int S_BM = 64;
constexpr int S_BN = 64;
constexpr int S_THREADS = 128;
constexpr int S_A_BYTES = S_BM * ROWB;           // 9216
constexpr int S_B_BYTES = S_BN * ROWB;           // 9216
constexpr int S_STAGE   = S_A_BYTES + S_B_BYTES; // 18432
constexpr int S_BIAS    = 3 * S_STAGE;           // 55296
constexpr int S_TOTAL   = S_BIAS + S_BN * 4;     // 55552
constexpr int S_NKB     = D_ / 64;               // 8

__global__ __launch_bounds__(S_THREADS, 1)
void layer1_mma(const float* __restrict__ b_enc)
{
    const int z = blockIdx.z;
    const __half* A; const __half* Bm; float* C; int M; const float* bias;
    if (z == 0) { A = g_Eh; Bm = g_Weh; C = g_E; M = ME; bias = b_enc; }
    else {
        if (blockIdx.y >= 7) return;
        A = g_Dh; Bm = g_Wdh; C = g_D; M = MD; bias = nullptr;
    }

    extern __shared__ char smem[];
    const uint32_t smem_base = smem_to_u32(smem);

    const int tid  = threadIdx.x;
    const int lane = tid & 31;
    const int wid  = tid >> 5;
    const int wm   = wid & 1;
    const int wn   = wid >> 1;

    const int brow = blockIdx.y * S_BM;
    const int bcol = blockIdx.x * S_BN;

    float* sb = reinterpret_cast<float*>(smem + S_BIAS);
    if (tid < S_BN) sb[tid] = bias ? bias[bcol + tid] : 0.0f;

    auto load_stage = [&](int kt, int s) {
        const uint32_t sba = smem_base + s * S_STAGE;
        const __half* ag = A + kt * 64;
        #pragma unroll
        for (int i = 0; i < 4; ++i) {
            int g = tid + i * S_THREADS;
            int row = g >> 3, gc = g & 7;
            int ra = min(brow + row, M - 1);
            CP_ASYNC16(sba + row * ROWB + gc * 16,
                       ag + (size_t)ra * D_ + gc * 8);
        }
        const uint32_t sbb = sba + S_A_BYTES;
        const __half* bg = Bm + kt * 64;
        #pragma unroll
        for (int i = 0; i < 4; ++i) {
            int g = tid + i * S_THREADS;
            int row = g >> 3, gc = g & 7;
            CP_ASYNC16(sbb + row * ROWB + gc * 16,
                       bg + (size_t)(bcol + row) * D_ + gc * 8);
        }
        CP_ASYNC_COMMIT();
    };

    float acc[2][4][4];
    #pragma unroll
    for (int i = 0; i < 2; ++i)
        #pragma unroll
        for (int j = 0; j < 4; ++j)
            #pragma unroll
            for (int r = 0; r < 4; ++r) acc[i][j][r] = 0.0f;

    load_stage(0, 0);
    load_stage(1, 1);

    const uint32_t aOff = (uint32_t)(wm * 32 + (lane & 15)) * ROWB + (lane >> 4) * 16;
    const uint32_t bOff = S_A_BYTES +
        (uint32_t)(wn * 32 + (lane & 7) + ((lane >> 4) << 3)) * ROWB +
        ((lane >> 3) & 1) * 16;

    int s = 0;
    #pragma unroll 1
    for (int kt = 0; kt < S_NKB; ++kt) {
        if (kt + 1 < S_NKB)
            asm volatile("cp.async.wait_group 1;" ::: "memory");
        else
            asm volatile("cp.async.wait_group 0;" ::: "memory");
        __syncthreads();

        if (kt + 2 < S_NKB) {
            int s2 = s + 2; if (s2 >= 3) s2 -= 3;
            load_stage(kt + 2, s2);
        }

        const uint32_t stg = smem_base + s * S_STAGE;

        #pragma unroll
        for (int ks = 0; ks < 4; ++ks) {
            const uint32_t kByte = ks * 32;
            uint32_t a[2][4];
            #pragma unroll
            for (int i = 0; i < 2; ++i)
                LDSM_X4(a[i][0], a[i][1], a[i][2], a[i][3],
                        stg + aOff + i * 16 * ROWB + kByte);
            uint32_t b[4][2];
            #pragma unroll
            for (int jj = 0; jj < 2; ++jj)
                LDSM_X4(b[2 * jj][0], b[2 * jj][1], b[2 * jj + 1][0], b[2 * jj + 1][1],
                        stg + bOff + jj * 16 * ROWB + kByte);
            #pragma unroll
            for (int i = 0; i < 2; ++i)
                #pragma unroll
                for (int j = 0; j < 4; ++j)
                    mma_f16(acc[i][j], a[i][0], a[i][1], a[i][2], a[i][3],
                            b[j][0], b[j][1]);
        }

        if (++s >= 3) s = 0;
    }

    #pragma unroll
    for (int i = 0; i < 2; ++i) {
        const int r0 = brow + wm * 32 + i * 16 + (lane >> 2);
        #pragma unroll
        for (int j = 0; j < 4; ++j) {
            const int cl = wn * 32 + j * 8 + 2 * (lane & 3);
            const float bx = sb[cl], by = sb[cl + 1];
            float2 v0 = { acc[i][j][0] + bx, acc[i][j][1] + by };
            float2 v1 = { acc[i][j][2] + bx, acc[i][j][3] + by };
            if (r0 < M)
                *reinterpret_cast<float2*>(C + (size_t)r0 * J_ + bcol + cl) = v0;
            if (r0 + 8 < M)
                *reinterpret_cast<float2*>(C + (size_t)(r0 + 8) * J_ + bcol + cl) = v1;
        }
    }
}

// ---------------------------------------------------------------------------
// tanh pass: one block per encoder row bt.
// ---------------------------------------------------------------------------
__global__ __launch_bounds__(256)
void tanh_broadcast_kernel()
{
    const int bt = blockIdx.x;
    const int b  = bt / T_;

    __shared__ float se[J_];
    {
        const float* erow = g_E + (size_t)bt * J_;
        for (int i = threadIdx.x; i < J_ / 4; i += 256)
            *reinterpret_cast<float4*>(se + i * 4) =
                *reinterpret_cast<const float4*>(erow + i * 4);
    }
    __syncthreads();

    const float* dbase = g_D + (size_t)b * U_ * J_;
    __half* zbase = g_Zh + (size_t)bt * U_ * J_;

    constexpr int UNITS = U_ * (J_ / 8);
    for (int idx = threadIdx.x; idx < UNITS; idx += 256) {
        const int u = idx >> 6;
        const int j = (idx & 63) * 8;
        const float* dp = dbase + (size_t)u * J_ + j;
        float4 d0 = *reinterpret_cast<const float4*>(dp);
        float4 d1 = *reinterpret_cast<const float4*>(dp + 4);
        float4 e0 = *reinterpret_cast<const float4*>(se + j);
        float4 e1 = *reinterpret_cast<const float4*>(se + j + 4);

        uint4 st;
        st.x = pack_h2(tanh_fast(e0.x + d0.x), tanh_fast(e0.y + d0.y));
        st.y = pack_h2(tanh_fast(e0.z + d0.z), tanh_fast(e0.w + d0.w));
        st.z = pack_h2(tanh_fast(e1.x + d1.x), tanh_fast(e1.y + d1.y));
        st.w = pack_h2(tanh_fast(e1.z + d1.z), tanh_fast(e1.w + d1.w));
        *reinterpret_cast<uint4*>(zbase + (size_t)u * J_ + j) = st;
    }
}

// ---------------------------------------------------------------------------
// Main GEMM: BM=64/BN=128/BK=64, 256 threads (8 warps 2x4, warp tile 32x32),
// 2-stage cp.async pipeline, ldmatrix fragment loads, 3 CTAs/SM.
// ---------------------------------------------------------------------------
constexpr int TC_BM = 64;
constexpr int TC_BN = 128;
constexpr int TC_BK = 64;
constexpr int TC_THREADS = 256;

constexpr int A_BYTES = TC_BM * ROWB;            // 9216
constexpr int B_BYTES = TC_BN * ROWB;            // 18432
constexpr int STAGE_BYTES = A_BYTES + B_BYTES;   // 27648
constexpr int SM_BIAS  = 2 * STAGE_BYTES;        // 55296
constexpr int SM_TOTAL = SM_BIAS + TC_BN * 4;    // 55808

__global__ __launch_bounds__(TC_THREADS, 3)
void joint_out_mma(const __half* __restrict__ Z,
                   const __half* __restrict__ Wh,
                   const float* __restrict__ bias,
                   float* __restrict__ out)
{
    extern __shared__ char smem[];
    const uint32_t smem_base = smem_to_u32(smem);

    const int tid  = threadIdx.x;
    const int lane = tid & 31;
    const int wid  = tid >> 5;
    const int wm   = wid & 1;        // 2 warp rows (32 rows each)
    const int wn   = wid >> 1;       // 4 warp cols (32 cols each)

    const int brow = blockIdx.y * TC_BM;
    const int bcol = blockIdx.x * TC_BN;

    float* sb = reinterpret_cast<float*>(smem + SM_BIAS);
    if (tid < TC_BN) sb[tid] = bias[bcol + tid];

    auto load_stage = [&](int kt, int s) {
        const uint32_t sba = smem_base + s * STAGE_BYTES;
        const __half* ag = Z + (size_t)brow * J_ + kt * TC_BK;
        #pragma unroll
        for (int i = 0; i < 2; ++i) {              // A: 64 rows * 8 = 512 granules
            int g = tid + i * TC_THREADS;
            int row = g >> 3, gc = g & 7;
            CP_ASYNC16(sba + row * ROWB + gc * 16,
                       ag + (size_t)row * J_ + gc * 8);
        }
        const uint32_t sbb = sba + A_BYTES;
        const __half* bg = Wh + (size_t)bcol * J_ + kt * TC_BK;
        #pragma unroll
        for (int i = 0; i < 4; ++i) {              // B: 128 rows * 8 = 1024 granules
            int g = tid + i * TC_THREADS;
            int row = g >> 3, gc = g & 7;
            CP_ASYNC16(sbb + row * ROWB + gc * 16,
                       bg + (size_t)row * J_ + gc * 8);
        }
        CP_ASYNC_COMMIT();
    };

    float acc[2][4][4];                // 2 m16-frags x 4 n8-frags
    #pragma unroll
    for (int i = 0; i < 2; ++i)
        #pragma unroll
        for (int j = 0; j < 4; ++j)
            #pragma unroll
            for (int r = 0; r < 4; ++r) acc[i][j][r] = 0.0f;

    load_stage(0, 0);

    const uint32_t aOff = (uint32_t)(wm * 32 + (lane & 15)) * ROWB + (lane >> 4) * 16;
    const uint32_t bOff = A_BYTES +
        (uint32_t)(wn * 32 + (lane & 7) + ((lane >> 4) << 3)) * ROWB +
        ((lane >> 3) & 1) * 16;

    constexpr int NKB = J_ / TC_BK;   // 8
    #pragma unroll 1
    for (int kt = 0; kt < NKB; ++kt) {
        const int s = kt & 1;
        if (kt + 1 < NKB) {
            load_stage(kt + 1, s ^ 1);
            asm volatile("cp.async.wait_group 1;" ::: "memory");
        } else {
            asm volatile("cp.async.wait_group 0;" ::: "memory");
        }
        __syncthreads();

        const uint32_t stg = smem_base + s * STAGE_BYTES;

        #pragma unroll
        for (int ks = 0; ks < 4; ++ks) {
            const uint32_t kByte = ks * 32;
            uint32_t a[2][4];
            #pragma unroll
            for (int i = 0; i < 2; ++i)
                LDSM_X4(a[i][0], a[i][1], a[i][2], a[i][3],
                        stg + aOff + i * 16 * ROWB + kByte);
            uint32_t b[4][2];
            #pragma unroll
            for (int jj = 0; jj < 2; ++jj)
                LDSM_X4(b[2 * jj][0], b[2 * jj][1], b[2 * jj + 1][0], b[2 * jj + 1][1],
                        stg + bOff + jj * 16 * ROWB + kByte);
            #pragma unroll
            for (int i = 0; i < 2; ++i)
                #pragma unroll
                for (int j = 0; j < 4; ++j)
                    mma_f16(acc[i][j], a[i][0], a[i][1], a[i][2], a[i][3],
                            b[j][0], b[j][1]);
        }

        __syncthreads();   // protect stage s before next iteration's load
    }

    #pragma unroll
    for (int i = 0; i < 2; ++i) {
        const int r0 = brow + wm * 32 + i * 16 + (lane >> 2);
        #pragma unroll
        for (int j = 0; j < 4; ++j) {
            const int cl = wn * 32 + j * 8 + 2 * (lane & 3);
            const float bx = sb[cl], by = sb[cl + 1];
            float2 v0 = { acc[i][j][0] + bx, acc[i][j][1] + by };
            float2 v1 = { acc[i][j][2] + bx, acc[i][j][3] + by };
            *reinterpret_cast<float2*>(out + (size_t)r0 * V_ + bcol + cl) = v0;
            *reinterpret_cast<float2*>(out + (size_t)(r0 + 8) * V_ + bcol + cl) = v1;
        }
    }
}

// ---------------------------------------------------------------------------
extern "C" void kernel_launch(void* const* d_in, const int* in_sizes, int n_in,
                              void* d_out, int out_size)
{
    const float* h_enc = (const float*)d_in[0];
    const float* h_dec = (const float*)d_in[1];
    const float* W_enc = (const float*)d_in[2];
    const float* b_enc = (const float*)d_in[3];
    const float* W_dec = (const float*)d_in[4];
    const float* W_out = (const float*)d_in[5];
    const float* b_out = (const float*)d_in[6];
    float* out = (float*)d_out;

    __half* Zh; cudaGetSymbolAddress((void**)&Zh, g_Zh);
    __half* Wh; cudaGetSymbolAddress((void**)&Wh, g_Wh);

    static bool attr_set = false;
    if (!attr_set) {
        cudaFuncSetAttribute(joint_out_mma,
                             cudaFuncAttributeMaxDynamicSharedMemorySize, SM_TOTAL);
        cudaFuncSetAttribute(layer1_mma,
                             cudaFuncAttributeMaxDynamicSharedMemorySize, S_TOTAL);
        attr_set = true;
    }

    // 1) fp32 -> fp16 converts for all 5 input tensors
    {
        dim3 grid(32, 1, 5);
        convert_kernel<<<grid, 256>>>(h_enc, h_dec, W_enc, W_dec, W_out);
    }
    // 2) E and D in one launch (fp16, K=512, fine tiles)
    {
        dim3 grid(J_ / S_BN, (ME + S_BM - 1) / S_BM, 2);   // (8, 25, 2)
        layer1_mma<<<grid, S_THREADS, S_TOTAL>>>(b_enc);
    }
    // 3) Zh = fp16(tanh_approx(E + D))
    {
        tanh_broadcast_kernel<<<ME, 256>>>();
    }
    // 4) out = Zh @ Wh^T + b_out  (3 CTAs/SM)
    {
        dim3 grid(V_ / TC_BN, MZ / TC_BM);   // (8, 1250)
        joint_out_mma<<<grid, TC_THREADS, SM_TOTAL>>>(Zh, Wh, b_out, out);
    }
}

// round 15
// speedup vs baseline: 1.1333x; 1.1333x over previous
#include <cuda_runtime.h>
#include <cuda_fp16.h>
#include <cstdint>
#include <math.h>

// Problem dims (fixed by the reference)
constexpr int B_  = 8;
constexpr int T_  = 200;
constexpr int U_  = 50;
constexpr int D_  = 512;
constexpr int J_  = 512;
constexpr int V_  = 1024;

constexpr int ME = B_ * T_;        // 1600
constexpr int MD = B_ * U_;        // 400
constexpr int MZ = B_ * T_ * U_;   // 80000

// Scratch (device globals: allocation-free per harness rules)
__device__ float  g_E[(size_t)ME * J_];
__device__ float  g_D[(size_t)MD * J_];
__device__ __half g_Zh[(size_t)MZ * J_];
__device__ __half g_Wh[(size_t)V_ * J_];
__device__ __half g_Eh[(size_t)ME * D_];     // h_enc fp16
__device__ __half g_Dh[(size_t)MD * D_];     // h_dec fp16
__device__ __half g_Weh[(size_t)J_ * D_];    // W_enc fp16
__device__ __half g_Wdh[(size_t)J_ * D_];    // W_dec fp16

// ---------------------------------------------------------------------------
__device__ __forceinline__ uint32_t smem_to_u32(const void* p) {
    uint32_t a;
    asm("{ .reg .u64 t; cvta.to.shared.u64 t, %1; cvt.u32.u64 %0, t; }"
        : "=r"(a) : "l"(p));
    return a;
}

#define CP_ASYNC16(saddr, gaddr) \
    asm volatile("cp.async.cg.shared.global [%0], [%1], 16;" :: "r"(saddr), "l"(gaddr) : "memory")
#define CP_ASYNC_COMMIT() asm volatile("cp.async.commit_group;" ::: "memory")

#define LDSM_X4(r0, r1, r2, r3, addr) \
    asm volatile("ldmatrix.sync.aligned.m8n8.x4.shared.b16 {%0,%1,%2,%3}, [%4];" \
        : "=r"(r0), "=r"(r1), "=r"(r2), "=r"(r3) : "r"(addr))

__device__ __forceinline__ float tanh_fast(float x) {
    float y;
    asm("tanh.approx.f32 %0, %1;" : "=f"(y) : "f"(x));
    return y;
}

__device__ __forceinline__ void mma_f16(float* d,
                                        uint32_t a0, uint32_t a1, uint32_t a2, uint32_t a3,
                                        uint32_t b0, uint32_t b1) {
    asm volatile(
        "mma.sync.aligned.m16n8k16.row.col.f32.f16.f16.f32 "
        "{%0,%1,%2,%3}, {%4,%5,%6,%7}, {%8,%9}, {%0,%1,%2,%3};"
        : "+f"(d[0]), "+f"(d[1]), "+f"(d[2]), "+f"(d[3])
        : "r"(a0), "r"(a1), "r"(a2), "r"(a3), "r"(b0), "r"(b1));
}

__device__ __forceinline__ uint32_t pack_h2(float x, float y) {
    __half2 h = __floats2half2_rn(x, y);
    return *reinterpret_cast<uint32_t*>(&h);
}

// Shared smem-row geometry for all mma kernels
constexpr int ROWH = 72;                         // 64 + 8 pad halves
constexpr int ROWB = ROWH * 2;                   // 144 B (16B-aligned, LDSM-safe)

// ---------------------------------------------------------------------------
// Convert kernel: plain fp32 -> fp16 for the 5 input tensors.
// ---------------------------------------------------------------------------
__global__ __launch_bounds__(256)
void convert_kernel(const float* __restrict__ h_enc,
                    const float* __restrict__ h_dec,
                    const float* __restrict__ W_enc,
                    const float* __restrict__ W_dec,
                    const float* __restrict__ W_out)
{
    const int z    = blockIdx.z;
    const int nthr = gridDim.x * 256;
    const int t0   = blockIdx.x * 256 + threadIdx.x;

    const float* src; __half* dst; int n;
    if      (z == 0) { src = h_enc; dst = g_Eh;  n = ME * D_; }
    else if (z == 1) { src = h_dec; dst = g_Dh;  n = MD * D_; }
    else if (z == 2) { src = W_enc; dst = g_Weh; n = J_ * D_; }
    else if (z == 3) { src = W_dec; dst = g_Wdh; n = J_ * D_; }
    else             { src = W_out; dst = g_Wh;  n = V_ * J_; }

    const int total8 = n / 8;
    for (int i = t0; i < total8; i += nthr) {
        float4 v0 = *reinterpret_cast<const float4*>(src + (size_t)i * 8);
        float4 v1 = *reinterpret_cast<const float4*>(src + (size_t)i * 8 + 4);
        uint4 st;
        st.x = pack_h2(v0.x, v0.y);
        st.y = pack_h2(v0.z, v0.w);
        st.z = pack_h2(v1.x, v1.y);
        st.w = pack_h2(v1.z, v1.w);
        *reinterpret_cast<uint4*>(dst + (size_t)i * 8) = st;
    }
}

// ---------------------------------------------------------------------------
// Layer-1 fp16 GEMM (K=512), fine tiles:
// BM=64, BN=64, BK=64, 128 threads (4 warps 2x2, warp tile 32x32).
// grid (8, 25, 2): z=0 -> E (bias b_enc), z=1 -> D (no bias, y<7).
// ---------------------------------------------------------------------------
constexpr int S_BM = 64;
constexpr int S_BN = 64;
constexpr int S_THREADS = 128;
constexpr int S_A_BYTES = S_BM * ROWB;           // 9216
constexpr int S_B_BYTES = S_BN * ROWB;           // 9216
constexpr int S_STAGE   = S_A_BYTES + S_B_BYTES; // 18432
constexpr int S_BIAS    = 3 * S_STAGE;           // 55296
constexpr int S_TOTAL   = S_BIAS + S_BN * 4;     // 55552
constexpr int S_NKB     = D_ / 64;               // 8

__global__ __launch_bounds__(S_THREADS, 1)
void layer1_mma(const float* __restrict__ b_enc)
{
    const int z = blockIdx.z;
    const __half* A; const __half* Bm; float* C; int M; const float* bias;
    if (z == 0) { A = g_Eh; Bm = g_Weh; C = g_E; M = ME; bias = b_enc; }
    else {
        if (blockIdx.y >= 7) return;
        A = g_Dh; Bm = g_Wdh; C = g_D; M = MD; bias = nullptr;
    }

    extern __shared__ char smem[];
    const uint32_t smem_base = smem_to_u32(smem);

    const int tid  = threadIdx.x;
    const int lane = tid & 31;
    const int wid  = tid >> 5;
    const int wm   = wid & 1;
    const int wn   = wid >> 1;

    const int brow = blockIdx.y * S_BM;
    const int bcol = blockIdx.x * S_BN;

    float* sb = reinterpret_cast<float*>(smem + S_BIAS);
    if (tid < S_BN) sb[tid] = bias ? bias[bcol + tid] : 0.0f;

    auto load_stage = [&](int kt, int s) {
        const uint32_t sba = smem_base + s * S_STAGE;
        const __half* ag = A + kt * 64;
        #pragma unroll
        for (int i = 0; i < 4; ++i) {
            int g = tid + i * S_THREADS;
            int row = g >> 3, gc = g & 7;
            int ra = min(brow + row, M - 1);
            CP_ASYNC16(sba + row * ROWB + gc * 16,
                       ag + (size_t)ra * D_ + gc * 8);
        }
        const uint32_t sbb = sba + S_A_BYTES;
        const __half* bg = Bm + kt * 64;
        #pragma unroll
        for (int i = 0; i < 4; ++i) {
            int g = tid + i * S_THREADS;
            int row = g >> 3, gc = g & 7;
            CP_ASYNC16(sbb + row * ROWB + gc * 16,
                       bg + (size_t)(bcol + row) * D_ + gc * 8);
        }
        CP_ASYNC_COMMIT();
    };

    float acc[2][4][4];
    #pragma unroll
    for (int i = 0; i < 2; ++i)
        #pragma unroll
        for (int j = 0; j < 4; ++j)
            #pragma unroll
            for (int r = 0; r < 4; ++r) acc[i][j][r] = 0.0f;

    load_stage(0, 0);
    load_stage(1, 1);

    const uint32_t aOff = (uint32_t)(wm * 32 + (lane & 15)) * ROWB + (lane >> 4) * 16;
    const uint32_t bOff = S_A_BYTES +
        (uint32_t)(wn * 32 + (lane & 7) + ((lane >> 4) << 3)) * ROWB +
        ((lane >> 3) & 1) * 16;

    int s = 0;
    #pragma unroll 1
    for (int kt = 0; kt < S_NKB; ++kt) {
        if (kt + 1 < S_NKB)
            asm volatile("cp.async.wait_group 1;" ::: "memory");
        else
            asm volatile("cp.async.wait_group 0;" ::: "memory");
        __syncthreads();

        if (kt + 2 < S_NKB) {
            int s2 = s + 2; if (s2 >= 3) s2 -= 3;
            load_stage(kt + 2, s2);
        }

        const uint32_t stg = smem_base + s * S_STAGE;

        #pragma unroll
        for (int ks = 0; ks < 4; ++ks) {
            const uint32_t kByte = ks * 32;
            uint32_t a[2][4];
            #pragma unroll
            for (int i = 0; i < 2; ++i)
                LDSM_X4(a[i][0], a[i][1], a[i][2], a[i][3],
                        stg + aOff + i * 16 * ROWB + kByte);
            uint32_t b[4][2];
            #pragma unroll
            for (int jj = 0; jj < 2; ++jj)
                LDSM_X4(b[2 * jj][0], b[2 * jj][1], b[2 * jj + 1][0], b[2 * jj + 1][1],
                        stg + bOff + jj * 16 * ROWB + kByte);
            #pragma unroll
            for (int i = 0; i < 2; ++i)
                #pragma unroll
                for (int j = 0; j < 4; ++j)
                    mma_f16(acc[i][j], a[i][0], a[i][1], a[i][2], a[i][3],
                            b[j][0], b[j][1]);
        }

        if (++s >= 3) s = 0;
    }

    #pragma unroll
    for (int i = 0; i < 2; ++i) {
        const int r0 = brow + wm * 32 + i * 16 + (lane >> 2);
        #pragma unroll
        for (int j = 0; j < 4; ++j) {
            const int cl = wn * 32 + j * 8 + 2 * (lane & 3);
            const float bx = sb[cl], by = sb[cl + 1];
            float2 v0 = { acc[i][j][0] + bx, acc[i][j][1] + by };
            float2 v1 = { acc[i][j][2] + bx, acc[i][j][3] + by };
            if (r0 < M)
                *reinterpret_cast<float2*>(C + (size_t)r0 * J_ + bcol + cl) = v0;
            if (r0 + 8 < M)
                *reinterpret_cast<float2*>(C + (size_t)(r0 + 8) * J_ + bcol + cl) = v1;
        }
    }
}

// ---------------------------------------------------------------------------
// tanh pass: one block per encoder row bt.
// ---------------------------------------------------------------------------
__global__ __launch_bounds__(256)
void tanh_broadcast_kernel()
{
    const int bt = blockIdx.x;
    const int b  = bt / T_;

    __shared__ float se[J_];
    {
        const float* erow = g_E + (size_t)bt * J_;
        for (int i = threadIdx.x; i < J_ / 4; i += 256)
            *reinterpret_cast<float4*>(se + i * 4) =
                *reinterpret_cast<const float4*>(erow + i * 4);
    }
    __syncthreads();

    const float* dbase = g_D + (size_t)b * U_ * J_;
    __half* zbase = g_Zh + (size_t)bt * U_ * J_;

    constexpr int UNITS = U_ * (J_ / 8);
    for (int idx = threadIdx.x; idx < UNITS; idx += 256) {
        const int u = idx >> 6;
        const int j = (idx & 63) * 8;
        const float* dp = dbase + (size_t)u * J_ + j;
        float4 d0 = *reinterpret_cast<const float4*>(dp);
        float4 d1 = *reinterpret_cast<const float4*>(dp + 4);
        float4 e0 = *reinterpret_cast<const float4*>(se + j);
        float4 e1 = *reinterpret_cast<const float4*>(se + j + 4);

        uint4 st;
        st.x = pack_h2(tanh_fast(e0.x + d0.x), tanh_fast(e0.y + d0.y));
        st.y = pack_h2(tanh_fast(e0.z + d0.z), tanh_fast(e0.w + d0.w));
        st.z = pack_h2(tanh_fast(e1.x + d1.x), tanh_fast(e1.y + d1.y));
        st.w = pack_h2(tanh_fast(e1.z + d1.z), tanh_fast(e1.w + d1.w));
        *reinterpret_cast<uint4*>(zbase + (size_t)u * J_ + j) = st;
    }
}

// ---------------------------------------------------------------------------
// Main GEMM: BM=128/BN=128/BK=64, 256 threads (8 warps 2x4, warp tile 64x32),
// 3-stage cp.async pipeline, ldmatrix loads with per-slice fragment
// double-buffering, 2 CTAs/SM.
// ---------------------------------------------------------------------------
constexpr int TC_BM = 128;
constexpr int TC_BN = 128;
constexpr int TC_BK = 64;
constexpr int TC_THREADS = 256;
constexpr int TC_STAGES = 3;

constexpr int A_BYTES = TC_BM * ROWB;            // 18432
constexpr int B_BYTES = TC_BN * ROWB;            // 18432
constexpr int STAGE_BYTES = A_BYTES + B_BYTES;   // 36864
constexpr int SM_BIAS  = TC_STAGES * STAGE_BYTES;      // 110592
constexpr int SM_TOTAL = SM_BIAS + TC_BN * 4;          // 111104

__global__ __launch_bounds__(TC_THREADS, 2)
void joint_out_mma(const __half* __restrict__ Z,
                   const __half* __restrict__ Wh,
                   const float* __restrict__ bias,
                   float* __restrict__ out)
{
    extern __shared__ char smem[];
    const uint32_t smem_base = smem_to_u32(smem);

    const int tid  = threadIdx.x;
    const int lane = tid & 31;
    const int wid  = tid >> 5;
    const int wm   = wid & 1;        // 2 warp rows (64 rows each)
    const int wn   = wid >> 1;       // 4 warp cols (32 cols each)

    const int brow = blockIdx.y * TC_BM;
    const int bcol = blockIdx.x * TC_BN;

    float* sb = reinterpret_cast<float*>(smem + SM_BIAS);
    if (tid < TC_BN) sb[tid] = bias[bcol + tid];

    auto load_stage = [&](int kt, int s) {
        const uint32_t sba = smem_base + s * STAGE_BYTES;
        const __half* ag = Z + (size_t)brow * J_ + kt * TC_BK;
        #pragma unroll
        for (int i = 0; i < 4; ++i) {              // A: 128 rows * 8 = 1024 granules
            int g = tid + i * TC_THREADS;
            int row = g >> 3, gc = g & 7;
            CP_ASYNC16(sba + row * ROWB + gc * 16,
                       ag + (size_t)row * J_ + gc * 8);
        }
        const uint32_t sbb = sba + A_BYTES;
        const __half* bg = Wh + (size_t)bcol * J_ + kt * TC_BK;
        #pragma unroll
        for (int i = 0; i < 4; ++i) {              // B: 128 rows * 8 = 1024 granules
            int g = tid + i * TC_THREADS;
            int row = g >> 3, gc = g & 7;
            CP_ASYNC16(sbb + row * ROWB + gc * 16,
                       bg + (size_t)row * J_ + gc * 8);
        }
        CP_ASYNC_COMMIT();
    };

    float acc[4][4][4];                // 4 m16-frags x 4 n8-frags
    #pragma unroll
    for (int i = 0; i < 4; ++i)
        #pragma unroll
        for (int j = 0; j < 4; ++j)
            #pragma unroll
            for (int r = 0; r < 4; ++r) acc[i][j][r] = 0.0f;

    load_stage(0, 0);
    load_stage(1, 1);

    const uint32_t aOff = (uint32_t)(wm * 64 + (lane & 15)) * ROWB + (lane >> 4) * 16;
    const uint32_t bOff = A_BYTES +
        (uint32_t)(wn * 32 + (lane & 7) + ((lane >> 4) << 3)) * ROWB +
        ((lane >> 3) & 1) * 16;

    // Fragment double buffers (2 slices in flight)
    uint32_t aF[2][4][4];
    uint32_t bF[2][4][2];

    auto load_frags = [&](uint32_t stg, int ks, int buf) {
        const uint32_t kByte = (uint32_t)ks * 32;
        #pragma unroll
        for (int i = 0; i < 4; ++i)
            LDSM_X4(aF[buf][i][0], aF[buf][i][1], aF[buf][i][2], aF[buf][i][3],
                    stg + aOff + i * 16 * ROWB + kByte);
        #pragma unroll
        for (int jj = 0; jj < 2; ++jj)
            LDSM_X4(bF[buf][2 * jj][0], bF[buf][2 * jj][1],
                    bF[buf][2 * jj + 1][0], bF[buf][2 * jj + 1][1],
                    stg + bOff + jj * 16 * ROWB + kByte);
    };

    int s = 0;
    constexpr int NKB = J_ / TC_BK;   // 8
    #pragma unroll 1
    for (int kt = 0; kt < NKB; ++kt) {
        if (kt + 1 < NKB)
            asm volatile("cp.async.wait_group 1;" ::: "memory");
        else
            asm volatile("cp.async.wait_group 0;" ::: "memory");
        __syncthreads();

        if (kt + 2 < NKB) {
            int s2 = s + 2; if (s2 >= TC_STAGES) s2 -= TC_STAGES;
            load_stage(kt + 2, s2);
        }

        const uint32_t stg = smem_base + s * STAGE_BYTES;

        load_frags(stg, 0, 0);
        #pragma unroll
        for (int ks = 0; ks < 4; ++ks) {
            const int cur = ks & 1;
            if (ks < 3) load_frags(stg, ks + 1, cur ^ 1);
            #pragma unroll
            for (int i = 0; i < 4; ++i)
                #pragma unroll
                for (int j = 0; j < 4; ++j)
                    mma_f16(acc[i][j],
                            aF[cur][i][0], aF[cur][i][1], aF[cur][i][2], aF[cur][i][3],
                            bF[cur][j][0], bF[cur][j][1]);
        }

        if (++s >= TC_STAGES) s = 0;
    }

    #pragma unroll
    for (int i = 0; i < 4; ++i) {
        const int r0 = brow + wm * 64 + i * 16 + (lane >> 2);
        #pragma unroll
        for (int j = 0; j < 4; ++j) {
            const int cl = wn * 32 + j * 8 + 2 * (lane & 3);
            const float bx = sb[cl], by = sb[cl + 1];
            float2 v0 = { acc[i][j][0] + bx, acc[i][j][1] + by };
            float2 v1 = { acc[i][j][2] + bx, acc[i][j][3] + by };
            *reinterpret_cast<float2*>(out + (size_t)r0 * V_ + bcol + cl) = v0;
            *reinterpret_cast<float2*>(out + (size_t)(r0 + 8) * V_ + bcol + cl) = v1;
        }
    }
}

// ---------------------------------------------------------------------------
extern "C" void kernel_launch(void* const* d_in, const int* in_sizes, int n_in,
                              void* d_out, int out_size)
{
    const float* h_enc = (const float*)d_in[0];
    const float* h_dec = (const float*)d_in[1];
    const float* W_enc = (const float*)d_in[2];
    const float* b_enc = (const float*)d_in[3];
    const float* W_dec = (const float*)d_in[4];
    const float* W_out = (const float*)d_in[5];
    const float* b_out = (const float*)d_in[6];
    float* out = (float*)d_out;

    __half* Zh; cudaGetSymbolAddress((void**)&Zh, g_Zh);
    __half* Wh; cudaGetSymbolAddress((void**)&Wh, g_Wh);

    static bool attr_set = false;
    if (!attr_set) {
        cudaFuncSetAttribute(joint_out_mma,
                             cudaFuncAttributeMaxDynamicSharedMemorySize, SM_TOTAL);
        cudaFuncSetAttribute(layer1_mma,
                             cudaFuncAttributeMaxDynamicSharedMemorySize, S_TOTAL);
        attr_set = true;
    }

    // 1) fp32 -> fp16 converts for all 5 input tensors
    {
        dim3 grid(32, 1, 5);
        convert_kernel<<<grid, 256>>>(h_enc, h_dec, W_enc, W_dec, W_out);
    }
    // 2) E and D in one launch (fp16, K=512, fine tiles)
    {
        dim3 grid(J_ / S_BN, (ME + S_BM - 1) / S_BM, 2);   // (8, 25, 2)
        layer1_mma<<<grid, S_THREADS, S_TOTAL>>>(b_enc);
    }
    // 3) Zh = fp16(tanh_approx(E + D))
    {
        tanh_broadcast_kernel<<<ME, 256>>>();
    }
    // 4) out = Zh @ Wh^T + b_out  (2 CTAs/SM, fragment double-buffered)
    {
        dim3 grid(V_ / TC_BN, MZ / TC_BM);   // (8, 625)
        joint_out_mma<<<grid, TC_THREADS, SM_TOTAL>>>(Zh, Wh, b_out, out);
    }
}

// round 16
// speedup vs baseline: 1.1705x; 1.0328x over previous
#include <cuda_runtime.h>
#include <cuda_fp16.h>
#include <cstdint>
#include <math.h>

// Problem dims (fixed by the reference)
constexpr int B_  = 8;
constexpr int T_  = 200;
constexpr int U_  = 50;
constexpr int D_  = 512;
constexpr int J_  = 512;
constexpr int V_  = 1024;

constexpr int ME = B_ * T_;        // 1600
constexpr int MD = B_ * U_;        // 400
constexpr int MZ = B_ * T_ * U_;   // 80000

// Scratch (device globals: allocation-free per harness rules)
__device__ float  g_E[(size_t)ME * J_];
__device__ float  g_D[(size_t)MD * J_];
__device__ __half g_Zh[(size_t)MZ * J_];
__device__ __half g_Wh[(size_t)V_ * J_];
__device__ __half g_Eh[(size_t)ME * D_];     // h_enc fp16
__device__ __half g_Dh[(size_t)MD * D_];     // h_dec fp16
__device__ __half g_Weh[(size_t)J_ * D_];    // W_enc fp16
__device__ __half g_Wdh[(size_t)J_ * D_];    // W_dec fp16

// ---------------------------------------------------------------------------
__device__ __forceinline__ uint32_t smem_to_u32(const void* p) {
    uint32_t a;
    asm("{ .reg .u64 t; cvta.to.shared.u64 t, %1; cvt.u32.u64 %0, t; }"
        : "=r"(a) : "l"(p));
    return a;
}

#define CP_ASYNC16(saddr, gaddr) \
    asm volatile("cp.async.cg.shared.global [%0], [%1], 16;" :: "r"(saddr), "l"(gaddr) : "memory")
#define CP_ASYNC_COMMIT() asm volatile("cp.async.commit_group;" ::: "memory")

#define LDSM_X4(r0, r1, r2, r3, addr) \
    asm volatile("ldmatrix.sync.aligned.m8n8.x4.shared.b16 {%0,%1,%2,%3}, [%4];" \
        : "=r"(r0), "=r"(r1), "=r"(r2), "=r"(r3) : "r"(addr))

__device__ __forceinline__ float tanh_fast(float x) {
    float y;
    asm("tanh.approx.f32 %0, %1;" : "=f"(y) : "f"(x));
    return y;
}

__device__ __forceinline__ void mma_f16(float* d,
                                        uint32_t a0, uint32_t a1, uint32_t a2, uint32_t a3,
                                        uint32_t b0, uint32_t b1) {
    asm volatile(
        "mma.sync.aligned.m16n8k16.row.col.f32.f16.f16.f32 "
        "{%0,%1,%2,%3}, {%4,%5,%6,%7}, {%8,%9}, {%0,%1,%2,%3};"
        : "+f"(d[0]), "+f"(d[1]), "+f"(d[2]), "+f"(d[3])
        : "r"(a0), "r"(a1), "r"(a2), "r"(a3), "r"(b0), "r"(b1));
}

__device__ __forceinline__ uint32_t pack_h2(float x, float y) {
    __half2 h = __floats2half2_rn(x, y);
    return *reinterpret_cast<uint32_t*>(&h);
}

// Shared smem-row geometry (padded rows, LDSM-proven)
constexpr int ROWH = 72;                         // 64 + 8 pad halves
constexpr int ROWB = ROWH * 2;                   // 144 B

// ---------------------------------------------------------------------------
// Convert kernel: plain fp32 -> fp16 for the 5 input tensors.
// ---------------------------------------------------------------------------
__global__ __launch_bounds__(256)
void convert_kernel(const float* __restrict__ h_enc,
                    const float* __restrict__ h_dec,
                    const float* __restrict__ W_enc,
                    const float* __restrict__ W_dec,
                    const float* __restrict__ W_out)
{
    const int z    = blockIdx.z;
    const int nthr = gridDim.x * 256;
    const int t0   = blockIdx.x * 256 + threadIdx.x;

    const float* src; __half* dst; int n;
    if      (z == 0) { src = h_enc; dst = g_Eh;  n = ME * D_; }
    else if (z == 1) { src = h_dec; dst = g_Dh;  n = MD * D_; }
    else if (z == 2) { src = W_enc; dst = g_Weh; n = J_ * D_; }
    else if (z == 3) { src = W_dec; dst = g_Wdh; n = J_ * D_; }
    else             { src = W_out; dst = g_Wh;  n = V_ * J_; }

    const int total8 = n / 8;
    for (int i = t0; i < total8; i += nthr) {
        float4 v0 = *reinterpret_cast<const float4*>(src + (size_t)i * 8);
        float4 v1 = *reinterpret_cast<const float4*>(src + (size_t)i * 8 + 4);
        uint4 st;
        st.x = pack_h2(v0.x, v0.y);
        st.y = pack_h2(v0.z, v0.w);
        st.z = pack_h2(v1.x, v1.y);
        st.w = pack_h2(v1.z, v1.w);
        *reinterpret_cast<uint4*>(dst + (size_t)i * 8) = st;
    }
}

// ---------------------------------------------------------------------------
// Layer-1 fp16 GEMM (K=512): BM=64, BN=64, BK=64, 128 threads (4 warps 2x2).
// grid (8, 25, 2): z=0 -> E (bias b_enc), z=1 -> D (no bias, y<7).
// ---------------------------------------------------------------------------
constexpr int S_BM = 64;
constexpr int S_BN = 64;
constexpr int S_THREADS = 128;
constexpr int S_A_BYTES = S_BM * ROWB;           // 9216
constexpr int S_B_BYTES = S_BN * ROWB;           // 9216
constexpr int S_STAGE   = S_A_BYTES + S_B_BYTES; // 18432
constexpr int S_BIAS    = 3 * S_STAGE;           // 55296
constexpr int S_TOTAL   = S_BIAS + S_BN * 4;     // 55552
constexpr int S_NKB     = D_ / 64;               // 8

__global__ __launch_bounds__(S_THREADS, 1)
void layer1_mma(const float* __restrict__ b_enc)
{
    const int z = blockIdx.z;
    const __half* A; const __half* Bm; float* C; int M; const float* bias;
    if (z == 0) { A = g_Eh; Bm = g_Weh; C = g_E; M = ME; bias = b_enc; }
    else {
        if (blockIdx.y >= 7) return;
        A = g_Dh; Bm = g_Wdh; C = g_D; M = MD; bias = nullptr;
    }

    extern __shared__ char smem[];
    const uint32_t smem_base = smem_to_u32(smem);

    const int tid  = threadIdx.x;
    const int lane = tid & 31;
    const int wid  = tid >> 5;
    const int wm   = wid & 1;
    const int wn   = wid >> 1;

    const int brow = blockIdx.y * S_BM;
    const int bcol = blockIdx.x * S_BN;

    float* sb = reinterpret_cast<float*>(smem + S_BIAS);
    if (tid < S_BN) sb[tid] = bias ? bias[bcol + tid] : 0.0f;

    auto load_stage = [&](int kt, int s) {
        const uint32_t sba = smem_base + s * S_STAGE;
        const __half* ag = A + kt * 64;
        #pragma unroll
        for (int i = 0; i < 4; ++i) {
            int g = tid + i * S_THREADS;
            int row = g >> 3, gc = g & 7;
            int ra = min(brow + row, M - 1);
            CP_ASYNC16(sba + row * ROWB + gc * 16,
                       ag + (size_t)ra * D_ + gc * 8);
        }
        const uint32_t sbb = sba + S_A_BYTES;
        const __half* bg = Bm + kt * 64;
        #pragma unroll
        for (int i = 0; i < 4; ++i) {
            int g = tid + i * S_THREADS;
            int row = g >> 3, gc = g & 7;
            CP_ASYNC16(sbb + row * ROWB + gc * 16,
                       bg + (size_t)(bcol + row) * D_ + gc * 8);
        }
        CP_ASYNC_COMMIT();
    };

    float acc[2][4][4];
    #pragma unroll
    for (int i = 0; i < 2; ++i)
        #pragma unroll
        for (int j = 0; j < 4; ++j)
            #pragma unroll
            for (int r = 0; r < 4; ++r) acc[i][j][r] = 0.0f;

    load_stage(0, 0);
    load_stage(1, 1);

    const uint32_t aOff = (uint32_t)(wm * 32 + (lane & 15)) * ROWB + (lane >> 4) * 16;
    const uint32_t bOff = S_A_BYTES +
        (uint32_t)(wn * 32 + (lane & 7) + ((lane >> 4) << 3)) * ROWB +
        ((lane >> 3) & 1) * 16;

    int s = 0;
    #pragma unroll 1
    for (int kt = 0; kt < S_NKB; ++kt) {
        if (kt + 1 < S_NKB)
            asm volatile("cp.async.wait_group 1;" ::: "memory");
        else
            asm volatile("cp.async.wait_group 0;" ::: "memory");
        __syncthreads();

        if (kt + 2 < S_NKB) {
            int s2 = s + 2; if (s2 >= 3) s2 -= 3;
            load_stage(kt + 2, s2);
        }

        const uint32_t stg = smem_base + s * S_STAGE;

        #pragma unroll
        for (int ks = 0; ks < 4; ++ks) {
            const uint32_t kByte = ks * 32;
            uint32_t a[2][4];
            #pragma unroll
            for (int i = 0; i < 2; ++i)
                LDSM_X4(a[i][0], a[i][1], a[i][2], a[i][3],
                        stg + aOff + i * 16 * ROWB + kByte);
            uint32_t b[4][2];
            #pragma unroll
            for (int jj = 0; jj < 2; ++jj)
                LDSM_X4(b[2 * jj][0], b[2 * jj][1], b[2 * jj + 1][0], b[2 * jj + 1][1],
                        stg + bOff + jj * 16 * ROWB + kByte);
            #pragma unroll
            for (int i = 0; i < 2; ++i)
                #pragma unroll
                for (int j = 0; j < 4; ++j)
                    mma_f16(acc[i][j], a[i][0], a[i][1], a[i][2], a[i][3],
                            b[j][0], b[j][1]);
        }

        if (++s >= 3) s = 0;
    }

    #pragma unroll
    for (int i = 0; i < 2; ++i) {
        const int r0 = brow + wm * 32 + i * 16 + (lane >> 2);
        #pragma unroll
        for (int j = 0; j < 4; ++j) {
            const int cl = wn * 32 + j * 8 + 2 * (lane & 3);
            const float bx = sb[cl], by = sb[cl + 1];
            float2 v0 = { acc[i][j][0] + bx, acc[i][j][1] + by };
            float2 v1 = { acc[i][j][2] + bx, acc[i][j][3] + by };
            if (r0 < M)
                *reinterpret_cast<float2*>(C + (size_t)r0 * J_ + bcol + cl) = v0;
            if (r0 + 8 < M)
                *reinterpret_cast<float2*>(C + (size_t)(r0 + 8) * J_ + bcol + cl) = v1;
        }
    }
}

// ---------------------------------------------------------------------------
// tanh pass: one block per encoder row bt.
// ---------------------------------------------------------------------------
__global__ __launch_bounds__(256)
void tanh_broadcast_kernel()
{
    const int bt = blockIdx.x;
    const int b  = bt / T_;

    __shared__ float se[J_];
    {
        const float* erow = g_E + (size_t)bt * J_;
        for (int i = threadIdx.x; i < J_ / 4; i += 256)
            *reinterpret_cast<float4*>(se + i * 4) =
                *reinterpret_cast<const float4*>(erow + i * 4);
    }
    __syncthreads();

    const float* dbase = g_D + (size_t)b * U_ * J_;
    __half* zbase = g_Zh + (size_t)bt * U_ * J_;

    constexpr int UNITS = U_ * (J_ / 8);
    for (int idx = threadIdx.x; idx < UNITS; idx += 256) {
        const int u = idx >> 6;
        const int j = (idx & 63) * 8;
        const float* dp = dbase + (size_t)u * J_ + j;
        float4 d0 = *reinterpret_cast<const float4*>(dp);
        float4 d1 = *reinterpret_cast<const float4*>(dp + 4);
        float4 e0 = *reinterpret_cast<const float4*>(se + j);
        float4 e1 = *reinterpret_cast<const float4*>(se + j + 4);

        uint4 st;
        st.x = pack_h2(tanh_fast(e0.x + d0.x), tanh_fast(e0.y + d0.y));
        st.y = pack_h2(tanh_fast(e0.z + d0.z), tanh_fast(e0.w + d0.w));
        st.z = pack_h2(tanh_fast(e1.x + d1.x), tanh_fast(e1.y + d1.y));
        st.w = pack_h2(tanh_fast(e1.z + d1.z), tanh_fast(e1.w + d1.w));
        *reinterpret_cast<uint4*>(zbase + (size_t)u * J_ + j) = st;
    }
}

// ---------------------------------------------------------------------------
// Main GEMM, persistent-B version:
//  - BM=128/BN=128, 256 threads, 8 warps (4 row-groups x 2 col-groups),
//    warp tile 32x64 (2 m16 x 8 n8, 6 LDSM per 16 HMMA).
//  - B tile (128 rows x full K=512) loaded ONCE per CTA into 131 KB of smem,
//    XOR-swizzled (granule ^ (row&7)) for conflict-free LDSM. Halves cp.async.
//  - A streamed through a 4-stage ring (18432 B/stage); each warp loads only
//    its own 16 rows, so the mainloop needs only a 2-warp named barrier.
//  - Each CTA processes TC_TILES=5 consecutive M-tiles (grid 8 x 125 = 625).
// ---------------------------------------------------------------------------
constexpr int TC_TILES = 5;
constexpr int TC_KK    = TC_TILES * 8;           // 40 k-chunks overall
constexpr int GB_BYTES = 128 * 1024;             // B: 128 rows x 1024 B
constexpr int GA_STAGE = 128 * ROWB;             // 18432
constexpr int GSM_A    = GB_BYTES;               // 131072
constexpr int GSM_BIAS = GSM_A + 4 * GA_STAGE;   // 204800
constexpr int GSM_TOTAL= GSM_BIAS + 128 * 4;     // 205312

__global__ __launch_bounds__(256)
void joint_out_mma(const __half* __restrict__ Z,
                   const __half* __restrict__ Wh,
                   const float* __restrict__ bias,
                   float* __restrict__ out)
{
    extern __shared__ char smem[];
    const uint32_t smem_base = smem_to_u32(smem);

    const int tid  = threadIdx.x;
    const int lane = tid & 31;
    const int wid  = tid >> 5;
    const int wm   = wid & 3;        // 4 row groups of 32
    const int wn   = wid >> 2;       // 2 col groups of 64

    const int bcol  = blockIdx.x * 128;
    const int brow0 = blockIdx.y * (TC_TILES * 128);

    // bias slab
    float* sb = reinterpret_cast<float*>(smem + GSM_BIAS);
    if (tid < 128) sb[tid] = bias[bcol + tid];

    // ---- B load (once): 128 rows x 64 granules, swizzled ----
    #pragma unroll
    for (int it = 0; it < 32; ++it) {
        int G = tid + it * 256;
        int n = G >> 6, g = G & 63;
        CP_ASYNC16(smem_base + (uint32_t)n * 1024 + (uint32_t)((g ^ (n & 7)) << 4),
                   Wh + (size_t)(bcol + n) * J_ + g * 8);
    }
    CP_ASYNC_COMMIT();
    asm volatile("cp.async.wait_group 0;" ::: "memory");
    __syncthreads();

    // ---- per-warp A loader: 16 rows (wm group, wn half) ----
    const int rowOff = wm * 32 + wn * 16;
    auto load_A = [&](int kload) {
        const int t  = kload >> 3;
        const int kt = kload & 7;
        const __half* ag = Z + (size_t)(brow0 + t * 128 + rowOff) * J_ + kt * 64;
        const uint32_t ad = smem_base + GSM_A + (kload & 3) * GA_STAGE + rowOff * ROWB;
        #pragma unroll
        for (int i = 0; i < 4; ++i) {
            int idx = lane + i * 32;
            int r16 = idx >> 3, g = idx & 7;
            CP_ASYNC16(ad + r16 * ROWB + g * 16, ag + (size_t)r16 * J_ + g * 8);
        }
        CP_ASYNC_COMMIT();
    };
    load_A(0); load_A(1); load_A(2);

    // ---- LDSM addressing ----
    const uint32_t aOff = (uint32_t)(wm * 32 + (lane & 15)) * ROWB + (lane >> 4) * 16;
    uint32_t bRowA[4], bRx[4];
    #pragma unroll
    for (int jj = 0; jj < 4; ++jj) {
        int r = wn * 64 + jj * 16 + (lane & 7) + ((lane >> 4) << 3);
        bRowA[jj] = smem_base + (uint32_t)r * 1024;
        bRx[jj]   = (uint32_t)(r & 7);
    }
    const uint32_t bGoff = (lane >> 3) & 1;

    float acc[2][8][4];
    #pragma unroll
    for (int i = 0; i < 2; ++i)
        #pragma unroll
        for (int j = 0; j < 8; ++j)
            #pragma unroll
            for (int r = 0; r < 4; ++r) acc[i][j][r] = 0.0f;

    const int barid = 1 + wm;

    #pragma unroll 1
    for (int kk = 0; kk < TC_KK; ++kk) {
        const int s  = kk & 3;
        const int kt = kk & 7;

        asm volatile("cp.async.wait_group 2;" ::: "memory");
        asm volatile("bar.sync %0, 64;" :: "r"(barid) : "memory");

        int kload = kk + 3;
        if (kload >= TC_KK) kload = TC_KK - 1;   // redundant reload, harmless
        load_A(kload);

        const uint32_t sA = smem_base + GSM_A + s * GA_STAGE;

        #pragma unroll
        for (int ks = 0; ks < 4; ++ks) {
            uint32_t a[2][4];
            #pragma unroll
            for (int i = 0; i < 2; ++i)
                LDSM_X4(a[i][0], a[i][1], a[i][2], a[i][3],
                        sA + aOff + i * 16 * ROWB + ks * 32);
            uint32_t b[8][2];
            #pragma unroll
            for (int jj = 0; jj < 4; ++jj) {
                uint32_t gsel = ((uint32_t)(kt * 8 + 2 * ks) + bGoff) ^ bRx[jj];
                LDSM_X4(b[2 * jj][0], b[2 * jj][1], b[2 * jj + 1][0], b[2 * jj + 1][1],
                        bRowA[jj] + (gsel << 4));
            }
            #pragma unroll
            for (int i = 0; i < 2; ++i)
                #pragma unroll
                for (int j = 0; j < 8; ++j)
                    mma_f16(acc[i][j], a[i][0], a[i][1], a[i][2], a[i][3],
                            b[j][0], b[j][1]);
        }

        if (kt == 7) {
            // epilogue for tile t = kk>>3 (warp-private rows/cols, no barrier)
            const int browT = brow0 + (kk >> 3) * 128;
            #pragma unroll
            for (int i = 0; i < 2; ++i) {
                const int r0 = browT + wm * 32 + i * 16 + (lane >> 2);
                #pragma unroll
                for (int j = 0; j < 8; ++j) {
                    const int cl = wn * 64 + j * 8 + 2 * (lane & 3);
                    const float bx = sb[cl], by = sb[cl + 1];
                    float2 v0 = { acc[i][j][0] + bx, acc[i][j][1] + by };
                    float2 v1 = { acc[i][j][2] + bx, acc[i][j][3] + by };
                    *reinterpret_cast<float2*>(out + (size_t)r0 * V_ + bcol + cl) = v0;
                    *reinterpret_cast<float2*>(out + (size_t)(r0 + 8) * V_ + bcol + cl) = v1;
                    acc[i][j][0] = 0.0f; acc[i][j][1] = 0.0f;
                    acc[i][j][2] = 0.0f; acc[i][j][3] = 0.0f;
                }
            }
        }
    }
}

// ---------------------------------------------------------------------------
extern "C" void kernel_launch(void* const* d_in, const int* in_sizes, int n_in,
                              void* d_out, int out_size)
{
    const float* h_enc = (const float*)d_in[0];
    const float* h_dec = (const float*)d_in[1];
    const float* W_enc = (const float*)d_in[2];
    const float* b_enc = (const float*)d_in[3];
    const float* W_dec = (const float*)d_in[4];
    const float* W_out = (const float*)d_in[5];
    const float* b_out = (const float*)d_in[6];
    float* out = (float*)d_out;

    __half* Zh; cudaGetSymbolAddress((void**)&Zh, g_Zh);
    __half* Wh; cudaGetSymbolAddress((void**)&Wh, g_Wh);

    static bool attr_set = false;
    if (!attr_set) {
        cudaFuncSetAttribute(joint_out_mma,
                             cudaFuncAttributeMaxDynamicSharedMemorySize, GSM_TOTAL);
        cudaFuncSetAttribute(layer1_mma,
                             cudaFuncAttributeMaxDynamicSharedMemorySize, S_TOTAL);
        attr_set = true;
    }

    // 1) fp32 -> fp16 converts for all 5 input tensors
    {
        dim3 grid(32, 1, 5);
        convert_kernel<<<grid, 256>>>(h_enc, h_dec, W_enc, W_dec, W_out);
    }
    // 2) E and D in one launch (fp16, K=512, fine tiles)
    {
        dim3 grid(J_ / S_BN, (ME + S_BM - 1) / S_BM, 2);   // (8, 25, 2)
        layer1_mma<<<grid, S_THREADS, S_TOTAL>>>(b_enc);
    }
    // 3) Zh = fp16(tanh_approx(E + D))
    {
        tanh_broadcast_kernel<<<ME, 256>>>();
    }
    // 4) out = Zh @ Wh^T + b_out  (persistent-B, 5 M-tiles per CTA)
    {
        dim3 grid(V_ / 128, (MZ / 128) / TC_TILES);   // (8, 125)
        joint_out_mma<<<grid, 256, GSM_TOTAL>>>(Zh, Wh, b_out, out);
    }
}